// round 1
// baseline (speedup 1.0000x reference)
#include <cuda_runtime.h>
#include <cuda_bf16.h>
#include <math_constants.h>

// Problem constants
#define Bb 64
#define Ss 2048
#define Hh 1024
#define Aa 512

// Scratch (no allocation allowed -> __device__ globals)
__device__ float g_C[Bb * Aa];        // per-batch context projection + bias
__device__ float g_scores[Bb * Ss];   // raw attention scores (pre-softmax)

// ---------------------------------------------------------------------------
// Kernel 1: C[b,a] = Wh_b[a] + x0[b]@W0[a] + x1[b]@W1[a] + x2[b]@W2[a]
// grid = 64 blocks (one per batch), 512 threads (one per a)
// ---------------------------------------------------------------------------
__global__ void ctx_kernel(const float* __restrict__ x0,
                           const float* __restrict__ x1,
                           const float* __restrict__ x2,
                           const float* __restrict__ W0,
                           const float* __restrict__ W1,
                           const float* __restrict__ W2,
                           const float* __restrict__ Whb) {
    __shared__ float xs[2048];
    int b = blockIdx.x;
    int t = threadIdx.x;

    xs[t]        = x0[b * 1024 + t];
    xs[t + 512]  = x0[b * 1024 + t + 512];
    xs[1024 + t] = x1[b * 512 + t];
    xs[1536 + t] = x2[b * 512 + t];
    __syncthreads();

    int a = t;
    float acc = Whb[a];

    const float4* w0 = (const float4*)(W0 + (size_t)a * 1024);
    const float4* xv = (const float4*)xs;
#pragma unroll 8
    for (int i = 0; i < 256; i++) {
        float4 w = w0[i]; float4 x = xv[i];
        acc += w.x * x.x + w.y * x.y + w.z * x.z + w.w * x.w;
    }
    const float4* w1 = (const float4*)(W1 + (size_t)a * 512);
    const float4* x1v = (const float4*)(xs + 1024);
#pragma unroll 8
    for (int i = 0; i < 128; i++) {
        float4 w = w1[i]; float4 x = x1v[i];
        acc += w.x * x.x + w.y * x.y + w.z * x.z + w.w * x.w;
    }
    const float4* w2 = (const float4*)(W2 + (size_t)a * 512);
    const float4* x2v = (const float4*)(xs + 1536);
#pragma unroll 8
    for (int i = 0; i < 128; i++) {
        float4 w = w2[i]; float4 x = x2v[i];
        acc += w.x * x.x + w.y * x.y + w.z * x.z + w.w * x.w;
    }
    g_C[b * Aa + a] = acc;
}

// ---------------------------------------------------------------------------
// Kernel 2: fused scores.
//   scores[b,s] = sum_a V[a] * relu( (X[b,s,:] @ Wh[a,:]) + C[b,a] )
// 128(s) x 128(a) tile per block, looped over 4 a-tiles internally; the [B,S,A]
// intermediate never hits gmem. Tiles fully past lengths[b] are skipped.
// block = 256 threads (16x16), 8x8 microtile, BK=16.
// grid = (S/128, B)
// ---------------------------------------------------------------------------
__global__ __launch_bounds__(256, 2)
void scores_kernel(const float* __restrict__ X,
                   const float* __restrict__ Wh,
                   const float* __restrict__ V,
                   const int* __restrict__ lengths) {
    int b  = blockIdx.y;
    int s0 = blockIdx.x * 128;
    int len = lengths[b];
    if (s0 >= len) return;  // masked region: never read by softmax

    __shared__ float Xs[16][132];   // [k][row]  (transposed, padded)
    __shared__ float Ws[16][132];   // [k][acol]
    __shared__ float cs[Aa];        // C[b,:]
    __shared__ float vs[Aa];        // V

    int tid = threadIdx.x;
    int tx = tid & 15;      // a-direction
    int ty = tid >> 4;      // s-direction

    for (int i = tid; i < Aa; i += 256) {
        cs[i] = g_C[b * Aa + i];
        vs[i] = V[i];
    }

    const float* Xb = X + ((size_t)b * Ss + s0) * Hh;

    float rowScore[8];
#pragma unroll
    for (int r = 0; r < 8; r++) rowScore[r] = 0.f;

    for (int at = 0; at < 4; at++) {
        int a0 = at * 128;
        float acc[8][8];
#pragma unroll
        for (int r = 0; r < 8; r++)
#pragma unroll
            for (int c = 0; c < 8; c++) acc[r][c] = 0.f;

        for (int k0 = 0; k0 < Hh; k0 += 16) {
            // load 128x16 X tile and 128x16 W tile (transposed into smem)
#pragma unroll
            for (int i = 0; i < 2; i++) {
                int t = tid + i * 256;
                int row = t >> 2;         // 0..127
                int kq  = t & 3;          // float4 index within 16
                float4 v = *(const float4*)(Xb + (size_t)row * Hh + k0 + kq * 4);
                Xs[kq * 4 + 0][row] = v.x;
                Xs[kq * 4 + 1][row] = v.y;
                Xs[kq * 4 + 2][row] = v.z;
                Xs[kq * 4 + 3][row] = v.w;
                float4 w = *(const float4*)(Wh + (size_t)(a0 + row) * Hh + k0 + kq * 4);
                Ws[kq * 4 + 0][row] = w.x;
                Ws[kq * 4 + 1][row] = w.y;
                Ws[kq * 4 + 2][row] = w.z;
                Ws[kq * 4 + 3][row] = w.w;
            }
            __syncthreads();

#pragma unroll
            for (int kk = 0; kk < 16; kk++) {
                float xf[8], wf[8];
                float4 t0 = *(const float4*)&Xs[kk][ty * 8];
                float4 t1 = *(const float4*)&Xs[kk][ty * 8 + 4];
                xf[0] = t0.x; xf[1] = t0.y; xf[2] = t0.z; xf[3] = t0.w;
                xf[4] = t1.x; xf[5] = t1.y; xf[6] = t1.z; xf[7] = t1.w;
                float4 u0 = *(const float4*)&Ws[kk][tx * 8];
                float4 u1 = *(const float4*)&Ws[kk][tx * 8 + 4];
                wf[0] = u0.x; wf[1] = u0.y; wf[2] = u0.z; wf[3] = u0.w;
                wf[4] = u1.x; wf[5] = u1.y; wf[6] = u1.z; wf[7] = u1.w;
#pragma unroll
                for (int r = 0; r < 8; r++)
#pragma unroll
                    for (int c = 0; c < 8; c++)
                        acc[r][c] = fmaf(xf[r], wf[c], acc[r][c]);
            }
            __syncthreads();
        }

        // epilogue: relu(acc + C) dot V, accumulated per s-row
#pragma unroll
        for (int c = 0; c < 8; c++) {
            int a = a0 + tx * 8 + c;
            float va = vs[a];
            float ca = cs[a];
#pragma unroll
            for (int r = 0; r < 8; r++) {
                float w = acc[r][c] + ca;
                rowScore[r] = fmaf(fmaxf(w, 0.f), va, rowScore[r]);
            }
        }
    }

    // reduce rowScore across the 16 tx lanes (tx = lane bits 0..3)
#pragma unroll
    for (int r = 0; r < 8; r++) {
#pragma unroll
        for (int off = 1; off < 16; off <<= 1)
            rowScore[r] += __shfl_xor_sync(0xffffffffu, rowScore[r], off);
    }
    if (tx == 0) {
#pragma unroll
        for (int r = 0; r < 8; r++)
            g_scores[b * Ss + s0 + ty * 8 + r] = rowScore[r];
    }
}

// ---------------------------------------------------------------------------
// Kernel 3: length-masked softmax over S. Writes attention_prob into
// d_out[B*H ... B*H + B*S). Masked positions get exactly 0.
// grid = 64, block = 256
// ---------------------------------------------------------------------------
__global__ void softmax_kernel(const int* __restrict__ lengths,
                               float* __restrict__ out) {
    int b = blockIdx.x;
    int len = lengths[b];
    int tid = threadIdx.x;
    const float* sc = g_scores + b * Ss;
    float* prob = out + Bb * Hh + (size_t)b * Ss;

    __shared__ float red[8];
    __shared__ float s_m, s_sum;

    // max
    float m = -CUDART_INF_F;
    for (int s = tid; s < len; s += 256) m = fmaxf(m, sc[s]);
#pragma unroll
    for (int o = 16; o > 0; o >>= 1) m = fmaxf(m, __shfl_xor_sync(~0u, m, o));
    if ((tid & 31) == 0) red[tid >> 5] = m;
    __syncthreads();
    if (tid == 0) {
        float mm = red[0];
#pragma unroll
        for (int i = 1; i < 8; i++) mm = fmaxf(mm, red[i]);
        s_m = mm;
    }
    __syncthreads();
    m = s_m;

    // sum of exp
    float sum = 0.f;
    for (int s = tid; s < len; s += 256) sum += expf(sc[s] - m);
#pragma unroll
    for (int o = 16; o > 0; o >>= 1) sum += __shfl_xor_sync(~0u, sum, o);
    if ((tid & 31) == 0) red[tid >> 5] = sum;
    __syncthreads();
    if (tid == 0) {
        float ss = 0.f;
#pragma unroll
        for (int i = 0; i < 8; i++) ss += red[i];
        s_sum = ss;
    }
    __syncthreads();
    float inv = 1.f / s_sum;

    for (int s = tid; s < Ss; s += 256)
        prob[s] = (s < len) ? expf(sc[s] - m) * inv : 0.f;
}

// ---------------------------------------------------------------------------
// Kernel 4: output[b,h] = sum_{s<len} prob[b,s] * X[b,s,h]
// grid = (H/256, B), block = 256 (one h per thread), length-capped loop.
// ---------------------------------------------------------------------------
__global__ void output_kernel(const float* __restrict__ X,
                              const int* __restrict__ lengths,
                              float* __restrict__ out) {
    int b = blockIdx.y;
    int h = blockIdx.x * 256 + threadIdx.x;
    int len = lengths[b];
    const float* prob = out + Bb * Hh + (size_t)b * Ss;
    const float* xb = X + ((size_t)b * Ss) * Hh + h;

    float a0 = 0.f, a1 = 0.f, a2 = 0.f, a3 = 0.f;
    int s = 0;
    for (; s + 4 <= len; s += 4) {
        a0 = fmaf(prob[s + 0], xb[(size_t)(s + 0) * Hh], a0);
        a1 = fmaf(prob[s + 1], xb[(size_t)(s + 1) * Hh], a1);
        a2 = fmaf(prob[s + 2], xb[(size_t)(s + 2) * Hh], a2);
        a3 = fmaf(prob[s + 3], xb[(size_t)(s + 3) * Hh], a3);
    }
    for (; s < len; s++) a0 = fmaf(prob[s], xb[(size_t)s * Hh], a0);
    out[(size_t)b * Hh + h] = (a0 + a1) + (a2 + a3);
}

// ---------------------------------------------------------------------------
extern "C" void kernel_launch(void* const* d_in, const int* in_sizes, int n_in,
                              void* d_out, int out_size) {
    const float* X   = (const float*)d_in[0];   // [64,2048,1024]
    const float* x0  = (const float*)d_in[1];   // [64,1024]
    const float* x1  = (const float*)d_in[2];   // [64,512]
    const float* x2  = (const float*)d_in[3];   // [64,512]
    const int*   len = (const int*)  d_in[4];   // [64]
    const float* WhW = (const float*)d_in[5];   // [512,1024]
    const float* WhB = (const float*)d_in[6];   // [512]
    const float* W0  = (const float*)d_in[7];   // [512,1024]
    const float* W1  = (const float*)d_in[8];   // [512,512]
    const float* W2  = (const float*)d_in[9];   // [512,512]
    const float* V   = (const float*)d_in[10];  // [1,512]
    float* out = (float*)d_out;                 // [64*1024 output | 64*2048 prob]

    ctx_kernel<<<Bb, 512>>>(x0, x1, x2, W0, W1, W2, WhB);
    scores_kernel<<<dim3(Ss / 128, Bb), 256>>>(X, WhW, V, len);
    softmax_kernel<<<Bb, 256>>>(len, out);
    output_kernel<<<dim3(Hh / 256, Bb), 256>>>(X, len, out);
}

// round 3
// speedup vs baseline: 2.1076x; 2.1076x over previous
#include <cuda_runtime.h>
#include <cuda_bf16.h>
#include <math_constants.h>
#include <cstdint>

#define Bb 64
#define Ss 2048
#define Hh 1024
#define Aa 512

// ---------------- device scratch (no allocations allowed) -------------------
__device__ float g_C[Bb * Aa];
__device__ float g_sc0[Bb * Ss];
__device__ float g_sc1[Bb * Ss];
__device__ float g_opart[Bb * 16 * Hh];
__device__ __nv_bfloat16 g_Whi[Aa * Hh];
__device__ __nv_bfloat16 g_Wlo[Aa * Hh];

// ---------------- helpers ---------------------------------------------------
__device__ __forceinline__ uint32_t smem_u32(const void* p) {
    uint32_t a;
    asm("{ .reg .u64 t; cvta.to.shared.u64 t, %1; cvt.u32.u64 %0, t; }" : "=r"(a) : "l"(p));
    return a;
}
__device__ __forceinline__ void cp_async16(uint32_t dst, const void* src) {
    asm volatile("cp.async.cg.shared.global [%0], [%1], 16;" :: "r"(dst), "l"(src) : "memory");
}
__device__ __forceinline__ void cp_commit() {
    asm volatile("cp.async.commit_group;" ::: "memory");
}
__device__ __forceinline__ void ldmx4(uint32_t& r0, uint32_t& r1, uint32_t& r2, uint32_t& r3,
                                      uint32_t addr) {
    asm volatile("ldmatrix.sync.aligned.m8n8.x4.shared.b16 {%0,%1,%2,%3}, [%4];"
                 : "=r"(r0), "=r"(r1), "=r"(r2), "=r"(r3) : "r"(addr));
}
__device__ __forceinline__ void mma_bf16(float* d, const uint32_t* a, const uint32_t* b) {
    asm volatile(
        "mma.sync.aligned.m16n8k16.row.col.f32.bf16.bf16.f32 "
        "{%0,%1,%2,%3}, {%4,%5,%6,%7}, {%8,%9}, {%0,%1,%2,%3};"
        : "+f"(d[0]), "+f"(d[1]), "+f"(d[2]), "+f"(d[3])
        : "r"(a[0]), "r"(a[1]), "r"(a[2]), "r"(a[3]), "r"(b[0]), "r"(b[1]));
}

// smem layout: 2 stages of [Xhi 10240 | Xlo 10240 | Whi 20480 | Wlo 20480]
#define STG_SZ   61440
#define OFF_XLO  10240
#define OFF_WHI  20480
#define OFF_WLO  40960
#define OFF_SCP  122880           // 512 floats
#define OFF_CS   124928           // 256 floats
#define OFF_VS   125952           // 256 floats
#define SMEM_SZ  126976

// ---------------------------------------------------------------------------
// prep_w: split Wh (fp32 [512][1024]) into bf16 hi/lo planes, row-major.
// grid 512, block 256 (one float4 per thread)
// ---------------------------------------------------------------------------
__global__ void prep_w(const float* __restrict__ Wh) {
    int a = blockIdx.x;
    int t = threadIdx.x;
    float4 v = *(const float4*)(Wh + (size_t)a * 1024 + t * 4);
    union U { __nv_bfloat16 h[4]; uint2 u; };
    U hi, lo;
    float f[4] = {v.x, v.y, v.z, v.w};
#pragma unroll
    for (int e = 0; e < 4; e++) {
        hi.h[e] = __float2bfloat16(f[e]);
        lo.h[e] = __float2bfloat16(f[e] - __bfloat162float(hi.h[e]));
    }
    *(uint2*)(g_Whi + (size_t)a * 1024 + t * 4) = hi.u;
    *(uint2*)(g_Wlo + (size_t)a * 1024 + t * 4) = lo.u;
}

// ---------------------------------------------------------------------------
// ctx: C[b,a] = Wh_b[a] + x0@W0[a] + x1@W1[a] + x2@W2[a]
// ---------------------------------------------------------------------------
__global__ void ctx_kernel(const float* __restrict__ x0,
                           const float* __restrict__ x1,
                           const float* __restrict__ x2,
                           const float* __restrict__ W0,
                           const float* __restrict__ W1,
                           const float* __restrict__ W2,
                           const float* __restrict__ Whb) {
    __shared__ float xs[2048];
    int b = blockIdx.x;
    int t = threadIdx.x;
    xs[t]        = x0[b * 1024 + t];
    xs[t + 512]  = x0[b * 1024 + t + 512];
    xs[1024 + t] = x1[b * 512 + t];
    xs[1536 + t] = x2[b * 512 + t];
    __syncthreads();
    int a = t;
    float acc = Whb[a];
    const float4* w0 = (const float4*)(W0 + (size_t)a * 1024);
    const float4* xv = (const float4*)xs;
#pragma unroll 8
    for (int i = 0; i < 256; i++) {
        float4 w = w0[i]; float4 x = xv[i];
        acc += w.x * x.x + w.y * x.y + w.z * x.z + w.w * x.w;
    }
    const float4* w1 = (const float4*)(W1 + (size_t)a * 512);
    const float4* x1v = (const float4*)(xs + 1024);
#pragma unroll 8
    for (int i = 0; i < 128; i++) {
        float4 w = w1[i]; float4 x = x1v[i];
        acc += w.x * x.x + w.y * x.y + w.z * x.z + w.w * x.w;
    }
    const float4* w2 = (const float4*)(W2 + (size_t)a * 512);
    const float4* x2v = (const float4*)(xs + 1536);
#pragma unroll 8
    for (int i = 0; i < 128; i++) {
        float4 w = w2[i]; float4 x = x2v[i];
        acc += w.x * x.x + w.y * x.y + w.z * x.z + w.w * x.w;
    }
    g_C[b * Aa + a] = acc;
}

// ---------------------------------------------------------------------------
// scores_mma: tensor-core (mma.sync bf16, bf16x3 split) fused scores.
//   D[128 s,256 a] = X @ Wh^T   then  score[s] += sum_a relu(D+C[a])*V[a]
// grid (16 s-tiles, 2 a-halves, 64 b), 512 threads (16 warps, 4x4),
// warp-tile 32x64, BK=32, double-buffered.
// ---------------------------------------------------------------------------
__global__ void __launch_bounds__(512)
scores_mma(const float* __restrict__ X,
           const float* __restrict__ V,
           const int* __restrict__ lengths) {
    extern __shared__ char smem[];
    int st = blockIdx.x, ah = blockIdx.y, b = blockIdx.z;
    int len = lengths[b];
    int s0 = st * 128;
    if (s0 >= len) return;

    int tid = threadIdx.x;
    int wid = tid >> 5;
    int lane = tid & 31;
    int wm = wid >> 2;       // 0..3 : rows wm*32
    int wn = wid & 3;        // 0..3 : cols wn*64

    float* cs = (float*)(smem + OFF_CS);
    float* vs = (float*)(smem + OFF_VS);
    if (tid < 256) {
        cs[tid] = g_C[b * Aa + ah * 256 + tid];
        vs[tid] = V[ah * 256 + tid];
    }

    uint32_t sbase = smem_u32(smem);

    // ---- per-thread constant mappings
    // W cp.async: 4 ops/thread
    int wlin = tid * 4;
    // X load/convert: 2 float4 per thread
    int xrow0 = (tid * 2) >> 3;
    int xq0 = (tid * 2) & 7;
    int xrow1 = (tid * 2 + 1) >> 3;
    int xq1 = (tid * 2 + 1) & 7;
    const float* Xb = X + ((size_t)b * Ss + s0) * Hh;

    // ldmatrix lane geometry
    uint32_t t8 = lane >> 3;
    uint32_t l7 = lane & 7;
    uint32_t arow[2], nrow[4];
#pragma unroll
    for (int i = 0; i < 2; i++)
        arow[i] = (wm * 32 + i * 16 + ((t8 & 1) << 3) + l7) * 80;
#pragma unroll
    for (int g = 0; g < 4; g++)
        nrow[g] = (wn * 64 + (g * 2 + (t8 >> 1)) * 8 + l7) * 80;
    uint32_t ka = (t8 >> 1) << 4;   // A k-tile byte offset within k16
    uint32_t kb_b = (t8 & 1) << 4;  // B k-tile byte offset within k16

    float acc[2][8][4];
#pragma unroll
    for (int i = 0; i < 2; i++)
#pragma unroll
        for (int j = 0; j < 8; j++)
#pragma unroll
            for (int r = 0; r < 4; r++) acc[i][j][r] = 0.f;

    // ---- helpers (macros as lambdas)
    auto issueW = [&](int ck, uint32_t stage_u32) {
#pragma unroll
        for (int i = 0; i < 4; i++) {
            int linear = wlin + i;
            int plane = linear >> 10;          // 0 hi, 1 lo
            int rem = linear & 1023;
            int row = rem >> 2;
            int chunk = rem & 3;
            const __nv_bfloat16* src =
                (plane ? g_Wlo : g_Whi) + ((size_t)(ah * 256 + row)) * 1024 + ck * 32 + chunk * 8;
            uint32_t dst = stage_u32 + OFF_WHI + plane * 20480 + row * 80 + chunk * 16;
            cp_async16(dst, src);
        }
        cp_commit();
    };
    auto loadX = [&](int ck, float4& v0, float4& v1) {
        v0 = *(const float4*)(Xb + (size_t)xrow0 * Hh + ck * 32 + xq0 * 4);
        v1 = *(const float4*)(Xb + (size_t)xrow1 * Hh + ck * 32 + xq1 * 4);
    };
    auto storeX = [&](char* stage_ptr, float4 v0, float4 v1) {
        union U { __nv_bfloat16 h[4]; uint2 u; };
        float f0[4] = {v0.x, v0.y, v0.z, v0.w};
        float f1[4] = {v1.x, v1.y, v1.z, v1.w};
        U h0, l0, h1, l1;
#pragma unroll
        for (int e = 0; e < 4; e++) {
            h0.h[e] = __float2bfloat16(f0[e]);
            l0.h[e] = __float2bfloat16(f0[e] - __bfloat162float(h0.h[e]));
            h1.h[e] = __float2bfloat16(f1[e]);
            l1.h[e] = __float2bfloat16(f1[e] - __bfloat162float(h1.h[e]));
        }
        *(uint2*)(stage_ptr + xrow0 * 80 + xq0 * 8) = h0.u;
        *(uint2*)(stage_ptr + OFF_XLO + xrow0 * 80 + xq0 * 8) = l0.u;
        *(uint2*)(stage_ptr + xrow1 * 80 + xq1 * 8) = h1.u;
        *(uint2*)(stage_ptr + OFF_XLO + xrow1 * 80 + xq1 * 8) = l1.u;
    };

    // ---- prologue: fill stages 0 and 1
    {
        float4 v0, v1;
        issueW(0, sbase);
        loadX(0, v0, v1);
        storeX(smem, v0, v1);
        issueW(1, sbase + STG_SZ);
        loadX(1, v0, v1);
        storeX(smem + STG_SZ, v0, v1);
    }

    // ---- main loop
    float4 pv0, pv1;
#pragma unroll 1
    for (int ck = 0; ck < 32; ck++) {
        if (ck == 31) asm volatile("cp.async.wait_group 0;" ::: "memory");
        else          asm volatile("cp.async.wait_group 1;" ::: "memory");
        __syncthreads();

        if (ck + 2 <= 31) loadX(ck + 2, pv0, pv1);   // prefetch into regs

        uint32_t sb = sbase + (uint32_t)(ck & 1) * STG_SZ;
#pragma unroll
        for (int sp = 0; sp < 3; sp++) {
            uint32_t Ab = sb + (sp == 2 ? OFF_XLO : 0u);
            uint32_t Bbs = sb + (sp == 1 ? OFF_WLO : OFF_WHI);
#pragma unroll
            for (int kf = 0; kf < 2; kf++) {
                uint32_t k16 = kf * 32;
                uint32_t a[2][4];
#pragma unroll
                for (int i = 0; i < 2; i++)
                    ldmx4(a[i][0], a[i][1], a[i][2], a[i][3], Ab + arow[i] + k16 + ka);
                uint32_t bf[8][2];
#pragma unroll
                for (int g = 0; g < 4; g++) {
                    uint32_t r0, r1, r2, r3;
                    ldmx4(r0, r1, r2, r3, Bbs + nrow[g] + k16 + kb_b);
                    bf[2 * g][0] = r0; bf[2 * g][1] = r1;
                    bf[2 * g + 1][0] = r2; bf[2 * g + 1][1] = r3;
                }
#pragma unroll
                for (int i = 0; i < 2; i++)
#pragma unroll
                    for (int j = 0; j < 8; j++)
                        mma_bf16(acc[i][j], a[i], bf[j]);
            }
        }
        __syncthreads();

        if (ck + 2 <= 31) {
            char* stage_ptr = smem + (ck & 1) * STG_SZ;
            storeX(stage_ptr, pv0, pv1);
            issueW(ck + 2, sbase + (uint32_t)(ck & 1) * STG_SZ);
        }
    }

    // ---- epilogue: relu(acc + C) dot V, reduce to per-row scores
    float rs[4] = {0.f, 0.f, 0.f, 0.f};
#pragma unroll
    for (int i = 0; i < 2; i++) {
#pragma unroll
        for (int j = 0; j < 8; j++) {
            int c = wn * 64 + j * 8 + (lane & 3) * 2;
            float v0 = vs[c], v1 = vs[c + 1];
            float c0 = cs[c], c1 = cs[c + 1];
            rs[i * 2 + 0] += fmaxf(acc[i][j][0] + c0, 0.f) * v0
                           + fmaxf(acc[i][j][1] + c1, 0.f) * v1;
            rs[i * 2 + 1] += fmaxf(acc[i][j][2] + c0, 0.f) * v0
                           + fmaxf(acc[i][j][3] + c1, 0.f) * v1;
        }
    }
#pragma unroll
    for (int r = 0; r < 4; r++) {
        rs[r] += __shfl_xor_sync(0xffffffffu, rs[r], 1);
        rs[r] += __shfl_xor_sync(0xffffffffu, rs[r], 2);
    }
    float* scp = (float*)(smem + OFF_SCP);
    if ((lane & 3) == 0) {
        int row = wm * 32 + (lane >> 2);
        scp[wn * 128 + row + 0]  = rs[0];
        scp[wn * 128 + row + 8]  = rs[1];
        scp[wn * 128 + row + 16] = rs[2];
        scp[wn * 128 + row + 24] = rs[3];
    }
    __syncthreads();
    if (tid < 128) {
        float v = scp[tid] + scp[128 + tid] + scp[256 + tid] + scp[384 + tid];
        (ah ? g_sc1 : g_sc0)[b * Ss + s0 + tid] = v;
    }
}

// ---------------------------------------------------------------------------
// softmax over s<len of (g_sc0+g_sc1); prob -> out[B*H ...]
// ---------------------------------------------------------------------------
__global__ void softmax_kernel(const int* __restrict__ lengths, float* __restrict__ out) {
    int b = blockIdx.x;
    int len = lengths[b];
    int tid = threadIdx.x;
    const float* a0 = g_sc0 + b * Ss;
    const float* a1 = g_sc1 + b * Ss;
    float* prob = out + Bb * Hh + (size_t)b * Ss;

    __shared__ float red[8];
    __shared__ float s_m, s_sum;

    float m = -CUDART_INF_F;
    for (int s = tid; s < len; s += 256) m = fmaxf(m, a0[s] + a1[s]);
#pragma unroll
    for (int o = 16; o > 0; o >>= 1) m = fmaxf(m, __shfl_xor_sync(~0u, m, o));
    if ((tid & 31) == 0) red[tid >> 5] = m;
    __syncthreads();
    if (tid == 0) {
        float mm = red[0];
#pragma unroll
        for (int i = 1; i < 8; i++) mm = fmaxf(mm, red[i]);
        s_m = mm;
    }
    __syncthreads();
    m = s_m;

    float sum = 0.f;
    for (int s = tid; s < len; s += 256) sum += expf(a0[s] + a1[s] - m);
#pragma unroll
    for (int o = 16; o > 0; o >>= 1) sum += __shfl_xor_sync(~0u, sum, o);
    if ((tid & 31) == 0) red[tid >> 5] = sum;
    __syncthreads();
    if (tid == 0) {
        float ss = 0.f;
#pragma unroll
        for (int i = 0; i < 8; i++) ss += red[i];
        s_sum = ss;
    }
    __syncthreads();
    float inv = 1.f / s_sum;

    for (int s = tid; s < Ss; s += 256)
        prob[s] = (s < len) ? expf(a0[s] + a1[s] - m) * inv : 0.f;
}

// ---------------------------------------------------------------------------
// output pass, two-phase
// ---------------------------------------------------------------------------
__global__ void output_partial(const float* __restrict__ X,
                               const int* __restrict__ lengths,
                               const float* __restrict__ out) {
    int sc = blockIdx.x, b = blockIdx.y;
    int len = lengths[b];
    int s0 = sc * 128;
    if (s0 >= len) return;
    int n = min(128, len - s0);
    int tid = threadIdx.x;
    const float4* Xb = (const float4*)X + ((size_t)(b * Ss + s0)) * 256 + tid;
    const float* prob = out + Bb * Hh + (size_t)b * Ss + s0;
    float4 acc = make_float4(0.f, 0.f, 0.f, 0.f);
#pragma unroll 4
    for (int s = 0; s < n; s++) {
        float p = __ldg(prob + s);
        float4 x = Xb[(size_t)s * 256];
        acc.x = fmaf(p, x.x, acc.x);
        acc.y = fmaf(p, x.y, acc.y);
        acc.z = fmaf(p, x.z, acc.z);
        acc.w = fmaf(p, x.w, acc.w);
    }
    ((float4*)g_opart)[(b * 16 + sc) * 256 + tid] = acc;
}

__global__ void output_reduce(const int* __restrict__ lengths, float* __restrict__ out) {
    int b = blockIdx.x;
    int tid = threadIdx.x;
    int kmax = min(16, (lengths[b] + 127) >> 7);
    float4 acc = make_float4(0.f, 0.f, 0.f, 0.f);
    for (int c = 0; c < kmax; c++) {
        float4 v = ((const float4*)g_opart)[(b * 16 + c) * 256 + tid];
        acc.x += v.x; acc.y += v.y; acc.z += v.z; acc.w += v.w;
    }
    ((float4*)out)[b * 256 + tid] = acc;
}

// ---------------------------------------------------------------------------
extern "C" void kernel_launch(void* const* d_in, const int* in_sizes, int n_in,
                              void* d_out, int out_size) {
    const float* X   = (const float*)d_in[0];
    const float* x0  = (const float*)d_in[1];
    const float* x1  = (const float*)d_in[2];
    const float* x2  = (const float*)d_in[3];
    const int*   len = (const int*)  d_in[4];
    const float* WhW = (const float*)d_in[5];
    const float* WhB = (const float*)d_in[6];
    const float* W0  = (const float*)d_in[7];
    const float* W1  = (const float*)d_in[8];
    const float* W2  = (const float*)d_in[9];
    const float* V   = (const float*)d_in[10];
    float* out = (float*)d_out;

    static bool attr_done = false;
    if (!attr_done) {
        cudaFuncSetAttribute(scores_mma, cudaFuncAttributeMaxDynamicSharedMemorySize, SMEM_SZ);
        attr_done = true;
    }

    prep_w<<<512, 256>>>(WhW);
    ctx_kernel<<<Bb, 512>>>(x0, x1, x2, W0, W1, W2, WhB);
    scores_mma<<<dim3(16, 2, Bb), 512, SMEM_SZ>>>(X, V, len);
    softmax_kernel<<<Bb, 256>>>(len, out);
    output_partial<<<dim3(16, Bb), 256>>>(X, len, out);
    output_reduce<<<Bb, 256>>>(len, out);
}